// round 6
// baseline (speedup 1.0000x reference)
#include <cuda_runtime.h>
#include <cstdint>

namespace {
constexpr int kB = 16, kH = 256, kC = 128, kW = 128;
constexpr long kCC = (long)kC * kC;
}

// Scratch (device globals: allocation-free contract).
__device__ float g_q[(size_t)kB * kW * kH * kC];   // q (B,W,H,C); reused as m5 (B,W,C,H)
__device__ float g_k[(size_t)kB * kW * kH * kC];   // k (B,W,H,C); reused as m6 (B,H,C,W)
__device__ float g_v[(size_t)kB * kW * kH * kC];   // v (B,W,H,C)
__device__ float g_s[(size_t)kB * kW * kC * kC];   // exp(scores) (B,W,D,C)
__device__ float g_wn[(size_t)kB * kW * kC * kC];  // wn (B,W,E,C)
__device__ float g_inv[(size_t)kB * kC * kC];      // 1/sum_w exp (B,D,C)

__device__ __forceinline__ uint32_t smem_u32(const void* p) {
  uint32_t a;
  asm("{ .reg .u64 t; cvta.to.shared.u64 t, %1; cvt.u32.u64 %0, t; }" : "=r"(a) : "l"(p));
  return a;
}
__device__ __forceinline__ uint32_t f2tf32(float f) {
  uint32_t r;
  asm("cvt.rna.tf32.f32 %0, %1;" : "=r"(r) : "f"(f));
  return r;
}
__device__ __forceinline__ void cpa4(uint32_t dst, const void* src) {
  asm volatile("cp.async.ca.shared.global [%0], [%1], 4;" :: "r"(dst), "l"(src));
}
__device__ __forceinline__ void cpa16(uint32_t dst, const void* src) {
  asm volatile("cp.async.cg.shared.global [%0], [%1], 16;" :: "r"(dst), "l"(src));
}
__device__ __forceinline__ void cpa_commit() {
  asm volatile("cp.async.commit_group;" ::: "memory");
}
__device__ __forceinline__ void cpa_wait1() {
  asm volatile("cp.async.wait_group 1;" ::: "memory");
}
__device__ __forceinline__ void cpa_wait0() {
  asm volatile("cp.async.wait_group 0;" ::: "memory");
}

// exp on the FMA pipe (no MUFU): exp(x) = 2^r * e^f, deg-5 Taylor on |f|<=ln2/2.
__device__ __forceinline__ float fast_exp(float x) {
  x = fminf(fmaxf(x, -30.f), 30.f);
  float r = rintf(x * 1.44269504f);
  float f = fmaf(r, -0.6931471805599453f, x);
  float p = 1.f + f * (1.f + f * (0.5f + f * (0.16666667f +
                f * (0.041666667f + f * 0.0083333333f))));
  return p * __int_as_float(((int)r + 127) << 23);
}

// SMEM row stride (words). 36 => fragment-load banks (4q+t)%32: conflict-free.
constexpr int kLds = 36;
constexpr int kBufW = 128 * kLds;  // words per buffer

// Async-copy one row-half (16 k-words) of a 128x32 chunk into smem [row][k].
// KC=true: k unit stride in gmem (4x 16B copies); else 16x 4B copies.
template <bool KC>
__device__ __forceinline__ void copy_chunk(uint32_t dst_base, const float* __restrict__ src,
                                           long sR, long sK, int k0, int row, int khalf) {
  uint32_t d = dst_base + (uint32_t)(row * kLds + khalf) * 4u;
  const float* p = src + (long)row * sR + (long)(k0 + khalf) * sK;
  if (KC) {
#pragma unroll
    for (int i = 0; i < 4; i++) cpa16(d + i * 16, p + i * 4);
  } else {
#pragma unroll
    for (int i = 0; i < 16; i++) cpa4(d + i * 4, p + (long)i * sK);
  }
}

// Core 128x128 GEMM body via mma.sync tf32 (fp32 accumulate), cp.async
// double-buffered over K-chunks of 32.
//   C[m,n] = alpha * sum_k A[m*sAm+k*sAk] * B[n*sBn+k*sBk] (+biases) ; C[m + n*sCn]
// EEPI: epilogue writes fast_exp(alpha*acc) (no bias). NORM: A *= nrm (same
// addressing as A) before tf32 conversion.
template <bool AKC, bool BKC, bool NORM, bool EEPI>
__device__ __forceinline__ void gemm_body(
    const float* __restrict__ A, long sAm, long sAk,
    const float* __restrict__ Bp, long sBn, long sBk,
    float* __restrict__ Cp, long sCn,
    const float* __restrict__ nrm,
    const float* __restrict__ bias_m, const float* __restrict__ bias_n,
    float alpha, int K) {
  __shared__ uint32_t As[2][kBufW];
  __shared__ uint32_t Bs[2][kBufW];
  __shared__ uint32_t Ns[NORM ? 2 * kBufW : 2];
  __shared__ float bmS[128], bnS[128];

  const int tid = threadIdx.x;
  const int lane = tid & 31, wid = tid >> 5;
  const int wm = (wid & 1) * 64, wn = (wid >> 1) * 32;
  const int row = tid >> 1, khalf = (tid & 1) * 16;

  const uint32_t aB[2] = {smem_u32(As[0]), smem_u32(As[1])};
  const uint32_t bB[2] = {smem_u32(Bs[0]), smem_u32(Bs[1])};
  const uint32_t nB[2] = {smem_u32(Ns), smem_u32(Ns) + (NORM ? kBufW * 4 : 0)};

  if (!EEPI && tid < 128) {
    bmS[tid] = bias_m ? bias_m[tid] : 0.f;
    bnS[tid] = bias_n ? bias_n[tid] : 0.f;
  }

  const int nch = K >> 5;
  // Prologue: prefetch chunks 0 and 1.
#pragma unroll
  for (int c = 0; c < 2; c++) {
    copy_chunk<AKC>(aB[c], A, sAm, sAk, c * 32, row, khalf);
    copy_chunk<BKC>(bB[c], Bp, sBn, sBk, c * 32, row, khalf);
    if (NORM) copy_chunk<AKC>(nB[c], nrm, sAm, sAk, c * 32, row, khalf);
    cpa_commit();
  }

  float acc[4][4][4];
#pragma unroll
  for (int i = 0; i < 4; i++)
#pragma unroll
    for (int j = 0; j < 4; j++)
#pragma unroll
      for (int c = 0; c < 4; c++) acc[i][j][c] = 0.f;

  for (int c = 0; c < nch; c++) {
    if (c + 2 <= nch) cpa_wait1(); else cpa_wait0();
    __syncthreads();

    const uint32_t* __restrict__ as = As[c & 1];
    const uint32_t* __restrict__ bs = Bs[c & 1];
    const uint32_t* __restrict__ ns = &Ns[NORM ? (c & 1) * kBufW : 0];

#pragma unroll
    for (int ks = 0; ks < 4; ks++) {
      const int kb = ks * 8 + (lane & 3);
      uint32_t af[4][4], bf[4][2];
#pragma unroll
      for (int im = 0; im < 4; im++) {
        int r0 = wm + im * 16 + (lane >> 2);
        int i00 = r0 * kLds + kb, i10 = (r0 + 8) * kLds + kb;
        if (NORM) {
          af[im][0] = f2tf32(__uint_as_float(as[i00]) * __uint_as_float(ns[i00]));
          af[im][1] = f2tf32(__uint_as_float(as[i10]) * __uint_as_float(ns[i10]));
          af[im][2] = f2tf32(__uint_as_float(as[i00 + 4]) * __uint_as_float(ns[i00 + 4]));
          af[im][3] = f2tf32(__uint_as_float(as[i10 + 4]) * __uint_as_float(ns[i10 + 4]));
        } else {
          af[im][0] = f2tf32(__uint_as_float(as[i00]));
          af[im][1] = f2tf32(__uint_as_float(as[i10]));
          af[im][2] = f2tf32(__uint_as_float(as[i00 + 4]));
          af[im][3] = f2tf32(__uint_as_float(as[i10 + 4]));
        }
      }
#pragma unroll
      for (int in = 0; in < 4; in++) {
        int n0 = (wn + in * 8 + (lane >> 2)) * kLds + kb;
        bf[in][0] = f2tf32(__uint_as_float(bs[n0]));
        bf[in][1] = f2tf32(__uint_as_float(bs[n0 + 4]));
      }
#pragma unroll
      for (int im = 0; im < 4; im++)
#pragma unroll
        for (int in = 0; in < 4; in++) {
          asm volatile(
              "mma.sync.aligned.m16n8k8.row.col.f32.tf32.tf32.f32 "
              "{%0,%1,%2,%3}, {%4,%5,%6,%7}, {%8,%9}, {%0,%1,%2,%3};"
              : "+f"(acc[im][in][0]), "+f"(acc[im][in][1]), "+f"(acc[im][in][2]),
                "+f"(acc[im][in][3])
              : "r"(af[im][0]), "r"(af[im][1]), "r"(af[im][2]), "r"(af[im][3]),
                "r"(bf[in][0]), "r"(bf[in][1]));
        }
    }
    __syncthreads();
    if (c + 2 < nch) {
      copy_chunk<AKC>(aB[c & 1], A, sAm, sAk, (c + 2) * 32, row, khalf);
      copy_chunk<BKC>(bB[c & 1], Bp, sBn, sBk, (c + 2) * 32, row, khalf);
      if (NORM) copy_chunk<AKC>(nB[c & 1], nrm, sAm, sAk, (c + 2) * 32, row, khalf);
      cpa_commit();
    }
  }

  const int g = lane >> 2, t2 = (lane & 3) * 2;
#pragma unroll
  for (int im = 0; im < 4; im++) {
    int m0 = wm + im * 16 + g;
    int m1 = m0 + 8;
    float bm0 = EEPI ? 0.f : bmS[m0], bm1 = EEPI ? 0.f : bmS[m1];
#pragma unroll
    for (int in = 0; in < 4; in++) {
      int n0 = wn + in * 8 + t2;
      int n1 = n0 + 1;
      if (EEPI) {
        Cp[(long)n0 * sCn + m0] = fast_exp(alpha * acc[im][in][0]);
        Cp[(long)n1 * sCn + m0] = fast_exp(alpha * acc[im][in][1]);
        Cp[(long)n0 * sCn + m1] = fast_exp(alpha * acc[im][in][2]);
        Cp[(long)n1 * sCn + m1] = fast_exp(alpha * acc[im][in][3]);
      } else {
        float bn0 = bnS[n0], bn1 = bnS[n1];
        Cp[(long)n0 * sCn + m0] = alpha * acc[im][in][0] + bm0 + bn0;
        Cp[(long)n1 * sCn + m0] = alpha * acc[im][in][1] + bm0 + bn1;
        Cp[(long)n0 * sCn + m1] = alpha * acc[im][in][2] + bm1 + bn0;
        Cp[(long)n1 * sCn + m1] = alpha * acc[im][in][3] + bm1 + bn1;
      }
    }
  }
}

// Fused QKV: grid (1, 3, B*H); y selects weight/bias/output; x tile reused via L2.
__global__ __launch_bounds__(256) void gemm_qkv(
    const float* __restrict__ x,
    const float* __restrict__ Wq, const float* __restrict__ Wk, const float* __restrict__ Wv,
    const float* __restrict__ bq, const float* __restrict__ bk, const float* __restrict__ bv,
    float* __restrict__ q, float* __restrict__ k, float* __restrict__ v) {
  const int z = blockIdx.z, y = blockIdx.y;
  const float* A = (y == 0) ? Wq : (y == 1) ? Wk : Wv;
  const float* bm = (y == 0) ? bq : (y == 1) ? bk : bv;
  float* C = ((y == 0) ? q : (y == 1) ? k : v) +
             (long)(z / kH) * ((long)kW * kH * kC) + (long)(z % kH) * kC;
  const float* B = x + (long)z * kC * kW;
  gemm_body<false, false, false, false>(A, 1, kC, B, 1, kW, C, (long)kH * kC,
                                        nullptr, bm, nullptr, 1.f, kC);
}

template <bool AKC, bool BKC, bool NORM, bool EEPI>
__global__ __launch_bounds__(256) void gemm_gen(
    const float* __restrict__ A, int a_div, long a_so, long a_si, long sAm, long sAk,
    const float* __restrict__ Bp, int b_div, long b_so, long b_si, long sBn, long sBk,
    float* __restrict__ Cp, int c_div, long c_so, long c_si, long sCn,
    const float* __restrict__ nrm_base, int nrm_div,
    const float* __restrict__ bias_m, const float* __restrict__ bias_n,
    float alpha, int K) {
  const int z = blockIdx.z, bx = blockIdx.x, by = blockIdx.y;
  A += (long)(z / a_div) * a_so + (long)(z % a_div) * a_si + (long)bx * 128 * sAm;
  Bp += (long)(z / b_div) * b_so + (long)(z % b_div) * b_si + (long)by * 128 * sBn;
  Cp += (long)(z / c_div) * c_so + (long)(z % c_div) * c_si + (long)bx * 128 +
        (long)by * 128 * sCn;
  const float* nrm = nullptr;
  if (NORM) nrm = nrm_base + (long)(z / nrm_div) * kCC + (long)bx * 128 * sAm;
  gemm_body<AKC, BKC, NORM, EEPI>(A, sAm, sAk, Bp, sBn, sBk, Cp, sCn, nrm,
                                  bias_m ? bias_m + bx * 128 : nullptr,
                                  bias_n ? bias_n + by * 128 : nullptr, alpha, K);
}

// Per-(b,d,c) reciprocal of sum over w of exp(scores) stored in s (B,W,D,C).
__global__ __launch_bounds__(256) void softmax_sum(const float* __restrict__ s,
                                                   float* __restrict__ inv) {
  long t = (long)blockIdx.x * blockDim.x + threadIdx.x;  // < B*C*C
  int b = (int)(t / kCC);
  int r = (int)(t % kCC);
  const float* p = s + (long)b * kW * kCC + r;
  float l = 0.f;
#pragma unroll 8
  for (int w = 0; w < kW; w++) l += p[(long)w * kCC];
  inv[t] = 1.f / l;
}

// Transpose m5 (B,W,C,H) -> m6 (B,H,C,W).
__global__ __launch_bounds__(256) void trans_wh(const float* __restrict__ in,
                                                float* __restrict__ out) {
  __shared__ float tile[32][33];
  int bc = blockIdx.z;
  int b = bc / kC, c = bc % kC;
  long ibase = (long)b * kW * kC * kH + (long)c * kH;
  long obase = (long)b * kH * kC * kW + (long)c * kW;
  int w0 = blockIdx.x * 32, h0 = blockIdx.y * 32;
  int txl = threadIdx.x;
#pragma unroll
  for (int i = threadIdx.y; i < 32; i += 8)
    tile[i][txl] = in[ibase + (long)(w0 + i) * (kC * kH) + h0 + txl];
  __syncthreads();
#pragma unroll
  for (int i = threadIdx.y; i < 32; i += 8)
    out[obase + (long)(h0 + i) * (kC * kW) + w0 + txl] = tile[txl][i];
}

extern "C" void kernel_launch(void* const* d_in, const int* in_sizes, int n_in,
                              void* d_out, int out_size) {
  (void)in_sizes; (void)n_in; (void)out_size;
  const float* x  = (const float*)d_in[0];
  const float* Wq = (const float*)d_in[1];
  const float* bq = (const float*)d_in[2];
  const float* Wk = (const float*)d_in[3];
  const float* bk = (const float*)d_in[4];
  const float* Wv = (const float*)d_in[5];
  const float* bv = (const float*)d_in[6];
  const float* Wn = (const float*)d_in[7];
  const float* bn = (const float*)d_in[8];
  const float* Wo = (const float*)d_in[9];
  const float* bo = (const float*)d_in[10];
  float* out = (float*)d_out;

  float *q, *k, *v, *s, *wn, *inv;
  cudaGetSymbolAddress((void**)&q, g_q);
  cudaGetSymbolAddress((void**)&k, g_k);
  cudaGetSymbolAddress((void**)&v, g_v);
  cudaGetSymbolAddress((void**)&s, g_s);
  cudaGetSymbolAddress((void**)&wn, g_wn);
  cudaGetSymbolAddress((void**)&inv, g_inv);

  const long HC = (long)kH * kC;
  const long CW = (long)kC * kW;
  const long CC = kCC;
  const long CH = (long)kC * kH;

  // Pass 1: fused Q/K/V projections. z=(b*H+h), y selects head. m=d, n=w, k=c.
  gemm_qkv<<<dim3(1, 3, kB * kH), 256>>>(x, Wq, Wk, Wv, bq, bk, bv, q, k, v);

  // Pass 2: s[b,w][c,d] = exp(sum_h q*k / sqrt(W)). z=(b*W+w). m=c, n=d, k=h.
  gemm_gen<false, false, false, true><<<dim3(1, 1, kB * kW), 256>>>(
      q, 1, HC, 0, 1, kC,
      k, 1, HC, 0, 1, kC,
      s, 1, CC, 0, kC,
      nullptr, 1, nullptr, nullptr, 0.08838834764831845f, kH);

  // Pass 3: softmax denominators.
  softmax_sum<<<(int)((kB * CC) / 256), 256>>>(s, inv);

  // Pass 4: wn[b,w][c,e] = sum_d (e*inv)[d,c]*Wn[d,e] + bn[e]. m=c, n=e, k=d.
  gemm_gen<false, false, true, false><<<dim3(1, 1, kB * kW), 256>>>(
      s, 1, CC, 0, 1, kC,
      Wn, 1, 0, 0, 1, kC,
      wn, 1, CC, 0, kC,
      inv, kW, nullptr, bn, 1.f, kC);

  // Pass 5: m[b,w][h,c] = sum_e v[h,e]*wn[e,c]. m=h (grid.x=2), n=c, k=e.
  gemm_gen<true, false, false, false><<<dim3(2, 1, kB * kW), 256>>>(
      v, 1, HC, 0, kC, 1,
      wn, 1, CC, 0, 1, kC,
      q, 1, CH, 0, kH,
      nullptr, 1, nullptr, nullptr, 1.f, kC);

  // Pass 5.5: transpose m5 (B,W,C,H) -> m6 (B,H,C,W).
  trans_wh<<<dim3(kW / 32, kH / 32, kB * kC), dim3(32, 8)>>>(q, k);

  // Pass 6: out[b,h][w,o] = sum_c m6[c,w]*Wo[c,o] + bo[o]. m=w, n=o, k=c.
  gemm_gen<false, false, false, false><<<dim3(1, 1, kB * kH), 256>>>(
      k, 1, CW, 0, 1, kW,
      Wo, 1, 0, 0, 1, kC,
      out, 1, CW, 0, kW,
      nullptr, 1, nullptr, bo, 1.f, kC);
}

// round 7
// speedup vs baseline: 1.3924x; 1.3924x over previous
#include <cuda_runtime.h>
#include <cstdint>

namespace {
constexpr int kB = 16, kH = 256, kC = 128, kW = 128;
constexpr long kCC = (long)kC * kC;
}

// Scratch (device globals: allocation-free contract).
__device__ float g_q[(size_t)kB * kW * kH * kC];   // q (B,W,H,C); reused as m5 (B,W,C,H)
__device__ float g_k[(size_t)kB * kW * kH * kC];   // k (B,W,H,C); reused as m6 (B,H,C,W)
__device__ float g_v[(size_t)kB * kW * kH * kC];   // v (B,W,H,C)
__device__ float g_s[(size_t)kB * kW * kC * kC];   // exp(scores) (B,W,D,C)
__device__ float g_wn[(size_t)kB * kW * kC * kC];  // wn (B,W,E,C)
__device__ float g_inv[(size_t)kB * kC * kC];      // 1/sum_w exp (B,D,C)

__device__ __forceinline__ uint32_t f2tf32(float f) {
  uint32_t r;
  asm("cvt.rna.tf32.f32 %0, %1;" : "=r"(r) : "f"(f));
  return r;
}

// exp on the FMA pipe (no MUFU): exp(x) = 2^r * e^f, deg-5 Taylor on |f|<=ln2/2.
__device__ __forceinline__ float fast_exp(float x) {
  x = fminf(fmaxf(x, -30.f), 30.f);
  float r = rintf(x * 1.44269504f);
  float f = fmaf(r, -0.6931471805599453f, x);
  float p = 1.f + f * (1.f + f * (0.5f + f * (0.16666667f +
                f * (0.041666667f + f * 0.0083333333f))));
  return p * __int_as_float(((int)r + 127) << 23);
}

// SMEM row stride (words). 36 => fragment-load banks (4q+t)%32: conflict-free.
constexpr int kLds = 36;
constexpr int kBufW = 128 * kLds;  // words per stage

// Load 16 k-words of one row into registers. KC=true: k unit stride (float4).
template <bool KC>
__device__ __forceinline__ void ldg16(float4 r[4], const float* __restrict__ p, long sK) {
  if (KC) {
#pragma unroll
    for (int i = 0; i < 4; i++) r[i] = reinterpret_cast<const float4*>(p)[i];
  } else {
#pragma unroll
    for (int i = 0; i < 4; i++) {
      r[i].x = p[(long)(i * 4 + 0) * sK];
      r[i].y = p[(long)(i * 4 + 1) * sK];
      r[i].z = p[(long)(i * 4 + 2) * sK];
      r[i].w = p[(long)(i * 4 + 3) * sK];
    }
  }
}

// Convert to tf32 (optionally *nrm first) and store 16 contiguous words to smem.
template <bool NORM>
__device__ __forceinline__ void sts16(uint32_t* __restrict__ dst, const float4 a[4],
                                      const float4 n[4]) {
#pragma unroll
  for (int i = 0; i < 4; i++) {
    float4 v = a[i];
    if (NORM) {
      v.x *= n[i].x; v.y *= n[i].y; v.z *= n[i].z; v.w *= n[i].w;
    }
    uint32_t t0 = f2tf32(v.x), t1 = f2tf32(v.y), t2 = f2tf32(v.z), t3 = f2tf32(v.w);
    asm volatile("st.shared.v4.b32 [%0], {%1,%2,%3,%4};"
                 :: "l"(dst + i * 4), "r"(t0), "r"(t1), "r"(t2), "r"(t3));
  }
}

// Core 128x128 GEMM body via mma.sync tf32 (fp32 accumulate).
// Register-staged double buffering: LDG chunk c+1 -> regs while MMA on smem
// stage c; STS to the other stage; one __syncthreads per chunk.
//   C[m,n] = alpha * sum_k A[m*sAm+k*sAk] * B[n*sBn+k*sBk] (+biases) ; C[m + n*sCn]
// EEPI: epilogue writes fast_exp(alpha*acc). NORM: A *= nrm (same addressing).
template <bool AKC, bool BKC, bool NORM, bool EEPI>
__device__ __forceinline__ void gemm_body(
    const float* __restrict__ A, long sAm, long sAk,
    const float* __restrict__ Bp, long sBn, long sBk,
    float* __restrict__ Cp, long sCn,
    const float* __restrict__ nrm,
    const float* __restrict__ bias_m, const float* __restrict__ bias_n,
    float alpha, int K) {
  __shared__ uint32_t As[2][kBufW];
  __shared__ uint32_t Bs[2][kBufW];
  __shared__ float bmS[128], bnS[128];

  const int tid = threadIdx.x;
  const int lane = tid & 31, wid = tid >> 5;
  const int wm = (wid & 1) * 64, wn = (wid >> 1) * 32;
  const int row = tid >> 1, khalf = (tid & 1) * 16;

  if (!EEPI && tid < 128) {
    bmS[tid] = bias_m ? bias_m[tid] : 0.f;
    bnS[tid] = bias_n ? bias_n[tid] : 0.f;
  }

  const float* Arow = A + (long)row * sAm + (long)khalf * sAk;
  const float* Brow = Bp + (long)row * sBn + (long)khalf * sBk;
  const float* Nrow = NORM ? nrm + (long)row * sAm + (long)khalf * sAk : nullptr;
  uint32_t* const sA = &As[0][0] + row * kLds + khalf;
  uint32_t* const sB = &Bs[0][0] + row * kLds + khalf;

  float4 pa[4], pb[4], pn[4];
  // Chunk 0.
  ldg16<AKC>(pa, Arow, sAk);
  ldg16<BKC>(pb, Brow, sBk);
  if (NORM) ldg16<AKC>(pn, Nrow, sAk);
  sts16<NORM>(sA, pa, pn);
  sts16<false>(sB, pb, nullptr);
  __syncthreads();

  float acc[4][4][4];
#pragma unroll
  for (int i = 0; i < 4; i++)
#pragma unroll
    for (int j = 0; j < 4; j++)
#pragma unroll
      for (int c = 0; c < 4; c++) acc[i][j][c] = 0.f;

  const int nch = K >> 5;
  for (int c = 0; c < nch; c++) {
    if (c + 1 < nch) {
      const long ko = (long)(c + 1) * 32;
      ldg16<AKC>(pa, Arow + ko * sAk, sAk);
      ldg16<BKC>(pb, Brow + ko * sBk, sBk);
      if (NORM) ldg16<AKC>(pn, Nrow + ko * sAk, sAk);
    }
    const uint32_t* __restrict__ as = As[c & 1];
    const uint32_t* __restrict__ bs = Bs[c & 1];

#pragma unroll
    for (int ks = 0; ks < 4; ks++) {
      const int kb = ks * 8 + (lane & 3);
      uint32_t af[4][4], bf[4][2];
#pragma unroll
      for (int im = 0; im < 4; im++) {
        int r0 = wm + im * 16 + (lane >> 2);
        af[im][0] = as[r0 * kLds + kb];
        af[im][1] = as[(r0 + 8) * kLds + kb];
        af[im][2] = as[r0 * kLds + kb + 4];
        af[im][3] = as[(r0 + 8) * kLds + kb + 4];
      }
#pragma unroll
      for (int in = 0; in < 4; in++) {
        int n0 = (wn + in * 8 + (lane >> 2)) * kLds + kb;
        bf[in][0] = bs[n0];
        bf[in][1] = bs[n0 + 4];
      }
#pragma unroll
      for (int im = 0; im < 4; im++)
#pragma unroll
        for (int in = 0; in < 4; in++) {
          asm volatile(
              "mma.sync.aligned.m16n8k8.row.col.f32.tf32.tf32.f32 "
              "{%0,%1,%2,%3}, {%4,%5,%6,%7}, {%8,%9}, {%0,%1,%2,%3};"
              : "+f"(acc[im][in][0]), "+f"(acc[im][in][1]), "+f"(acc[im][in][2]),
                "+f"(acc[im][in][3])
              : "r"(af[im][0]), "r"(af[im][1]), "r"(af[im][2]), "r"(af[im][3]),
                "r"(bf[in][0]), "r"(bf[in][1]));
        }
    }
    if (c + 1 < nch) {
      const int nb = (c + 1) & 1;
      sts16<NORM>(sA + nb * kBufW, pa, pn);
      sts16<false>(sB + nb * kBufW, pb, nullptr);
    }
    __syncthreads();
  }

  const int g = lane >> 2, t2 = (lane & 3) * 2;
#pragma unroll
  for (int im = 0; im < 4; im++) {
    int m0 = wm + im * 16 + g;
    int m1 = m0 + 8;
    float bm0 = EEPI ? 0.f : bmS[m0], bm1 = EEPI ? 0.f : bmS[m1];
#pragma unroll
    for (int in = 0; in < 4; in++) {
      int n0 = wn + in * 8 + t2;
      int n1 = n0 + 1;
      if (EEPI) {
        Cp[(long)n0 * sCn + m0] = fast_exp(alpha * acc[im][in][0]);
        Cp[(long)n1 * sCn + m0] = fast_exp(alpha * acc[im][in][1]);
        Cp[(long)n0 * sCn + m1] = fast_exp(alpha * acc[im][in][2]);
        Cp[(long)n1 * sCn + m1] = fast_exp(alpha * acc[im][in][3]);
      } else {
        float bn0 = bnS[n0], bn1 = bnS[n1];
        Cp[(long)n0 * sCn + m0] = alpha * acc[im][in][0] + bm0 + bn0;
        Cp[(long)n1 * sCn + m0] = alpha * acc[im][in][1] + bm0 + bn1;
        Cp[(long)n0 * sCn + m1] = alpha * acc[im][in][2] + bm1 + bn0;
        Cp[(long)n1 * sCn + m1] = alpha * acc[im][in][3] + bm1 + bn1;
      }
    }
  }
}

// Fused QKV: grid (1, 3, B*H); y selects weight/bias/output; x tile reused via L2.
__global__ __launch_bounds__(256) void gemm_qkv(
    const float* __restrict__ x,
    const float* __restrict__ Wq, const float* __restrict__ Wk, const float* __restrict__ Wv,
    const float* __restrict__ bq, const float* __restrict__ bk, const float* __restrict__ bv,
    float* __restrict__ q, float* __restrict__ k, float* __restrict__ v) {
  const int z = blockIdx.z, y = blockIdx.y;
  const float* A = (y == 0) ? Wq : (y == 1) ? Wk : Wv;
  const float* bm = (y == 0) ? bq : (y == 1) ? bk : bv;
  float* C = ((y == 0) ? q : (y == 1) ? k : v) +
             (long)(z / kH) * ((long)kW * kH * kC) + (long)(z % kH) * kC;
  const float* B = x + (long)z * kC * kW;
  gemm_body<false, false, false, false>(A, 1, kC, B, 1, kW, C, (long)kH * kC,
                                        nullptr, bm, nullptr, 1.f, kC);
}

template <bool AKC, bool BKC, bool NORM, bool EEPI>
__global__ __launch_bounds__(256) void gemm_gen(
    const float* __restrict__ A, int a_div, long a_so, long a_si, long sAm, long sAk,
    const float* __restrict__ Bp, int b_div, long b_so, long b_si, long sBn, long sBk,
    float* __restrict__ Cp, int c_div, long c_so, long c_si, long sCn,
    const float* __restrict__ nrm_base, int nrm_div,
    const float* __restrict__ bias_m, const float* __restrict__ bias_n,
    float alpha, int K) {
  const int z = blockIdx.z, bx = blockIdx.x, by = blockIdx.y;
  A += (long)(z / a_div) * a_so + (long)(z % a_div) * a_si + (long)bx * 128 * sAm;
  Bp += (long)(z / b_div) * b_so + (long)(z % b_div) * b_si + (long)by * 128 * sBn;
  Cp += (long)(z / c_div) * c_so + (long)(z % c_div) * c_si + (long)bx * 128 +
        (long)by * 128 * sCn;
  const float* nrm = nullptr;
  if (NORM) nrm = nrm_base + (long)(z / nrm_div) * kCC + (long)bx * 128 * sAm;
  gemm_body<AKC, BKC, NORM, EEPI>(A, sAm, sAk, Bp, sBn, sBk, Cp, sCn, nrm,
                                  bias_m ? bias_m + bx * 128 : nullptr,
                                  bias_n ? bias_n + by * 128 : nullptr, alpha, K);
}

// Per-(b,d,c) reciprocal of sum over w of exp(scores) stored in s (B,W,D,C).
__global__ __launch_bounds__(256) void softmax_sum(const float* __restrict__ s,
                                                   float* __restrict__ inv) {
  long t = (long)blockIdx.x * blockDim.x + threadIdx.x;  // < B*C*C
  int b = (int)(t / kCC);
  int r = (int)(t % kCC);
  const float* p = s + (long)b * kW * kCC + r;
  float l = 0.f;
#pragma unroll 8
  for (int w = 0; w < kW; w++) l += p[(long)w * kCC];
  inv[t] = 1.f / l;
}

// Transpose m5 (B,W,C,H) -> m6 (B,H,C,W).
__global__ __launch_bounds__(256) void trans_wh(const float* __restrict__ in,
                                                float* __restrict__ out) {
  __shared__ float tile[32][33];
  int bc = blockIdx.z;
  int b = bc / kC, c = bc % kC;
  long ibase = (long)b * kW * kC * kH + (long)c * kH;
  long obase = (long)b * kH * kC * kW + (long)c * kW;
  int w0 = blockIdx.x * 32, h0 = blockIdx.y * 32;
  int txl = threadIdx.x;
#pragma unroll
  for (int i = threadIdx.y; i < 32; i += 8)
    tile[i][txl] = in[ibase + (long)(w0 + i) * (kC * kH) + h0 + txl];
  __syncthreads();
#pragma unroll
  for (int i = threadIdx.y; i < 32; i += 8)
    out[obase + (long)(h0 + i) * (kC * kW) + w0 + txl] = tile[txl][i];
}

extern "C" void kernel_launch(void* const* d_in, const int* in_sizes, int n_in,
                              void* d_out, int out_size) {
  (void)in_sizes; (void)n_in; (void)out_size;
  const float* x  = (const float*)d_in[0];
  const float* Wq = (const float*)d_in[1];
  const float* bq = (const float*)d_in[2];
  const float* Wk = (const float*)d_in[3];
  const float* bk = (const float*)d_in[4];
  const float* Wv = (const float*)d_in[5];
  const float* bv = (const float*)d_in[6];
  const float* Wn = (const float*)d_in[7];
  const float* bn = (const float*)d_in[8];
  const float* Wo = (const float*)d_in[9];
  const float* bo = (const float*)d_in[10];
  float* out = (float*)d_out;

  float *q, *k, *v, *s, *wn, *inv;
  cudaGetSymbolAddress((void**)&q, g_q);
  cudaGetSymbolAddress((void**)&k, g_k);
  cudaGetSymbolAddress((void**)&v, g_v);
  cudaGetSymbolAddress((void**)&s, g_s);
  cudaGetSymbolAddress((void**)&wn, g_wn);
  cudaGetSymbolAddress((void**)&inv, g_inv);

  const long HC = (long)kH * kC;
  const long CW = (long)kC * kW;
  const long CC = kCC;
  const long CH = (long)kC * kH;

  // Pass 1: fused Q/K/V projections. z=(b*H+h), y selects head. m=d, n=w, k=c.
  gemm_qkv<<<dim3(1, 3, kB * kH), 256>>>(x, Wq, Wk, Wv, bq, bk, bv, q, k, v);

  // Pass 2: s[b,w][c,d] = exp(sum_h q*k / sqrt(W)). z=(b*W+w). m=c, n=d, k=h.
  gemm_gen<false, false, false, true><<<dim3(1, 1, kB * kW), 256>>>(
      q, 1, HC, 0, 1, kC,
      k, 1, HC, 0, 1, kC,
      s, 1, CC, 0, kC,
      nullptr, 1, nullptr, nullptr, 0.08838834764831845f, kH);

  // Pass 3: softmax denominators.
  softmax_sum<<<(int)((kB * CC) / 256), 256>>>(s, inv);

  // Pass 4: wn[b,w][c,e] = sum_d (e*inv)[d,c]*Wn[d,e] + bn[e]. m=c, n=e, k=d.
  gemm_gen<false, false, true, false><<<dim3(1, 1, kB * kW), 256>>>(
      s, 1, CC, 0, 1, kC,
      Wn, 1, 0, 0, 1, kC,
      wn, 1, CC, 0, kC,
      inv, kW, nullptr, bn, 1.f, kC);

  // Pass 5: m[b,w][h,c] = sum_e v[h,e]*wn[e,c]. m=h (grid.x=2), n=c, k=e.
  gemm_gen<true, false, false, false><<<dim3(2, 1, kB * kW), 256>>>(
      v, 1, HC, 0, kC, 1,
      wn, 1, CC, 0, 1, kC,
      q, 1, CH, 0, kH,
      nullptr, 1, nullptr, nullptr, 1.f, kC);

  // Pass 5.5: transpose m5 (B,W,C,H) -> m6 (B,H,C,W).
  trans_wh<<<dim3(kW / 32, kH / 32, kB * kC), dim3(32, 8)>>>(q, k);

  // Pass 6: out[b,h][w,o] = sum_c m6[c,w]*Wo[c,o] + bo[o]. m=w, n=o, k=c.
  gemm_gen<false, false, false, false><<<dim3(1, 1, kB * kH), 256>>>(
      k, 1, CW, 0, 1, kW,
      Wo, 1, 0, 0, 1, kC,
      out, 1, CW, 0, kW,
      nullptr, 1, nullptr, bo, 1.f, kC);
}

// round 8
// speedup vs baseline: 1.5645x; 1.1236x over previous
#include <cuda_runtime.h>
#include <cstdint>

namespace {
constexpr int kB = 16, kH = 256, kC = 128, kW = 128;
constexpr long kCC = (long)kC * kC;
}

// Scratch (device globals: allocation-free contract).
__device__ float g_q[(size_t)kB * kW * kH * kC];   // q (B,W,H,C); reused as m5 (B,W,C,H)
__device__ float g_k[(size_t)kB * kW * kH * kC];   // k (B,W,H,C); reused as m6 (B,H,C,W)
__device__ float g_v[(size_t)kB * kW * kH * kC];   // v (B,W,H,C)
__device__ float g_s[(size_t)kB * kW * kC * kC];   // exp(scores) (B,W,D,C)
__device__ float g_wn[(size_t)kB * kW * kC * kC];  // wn (B,W,E,C)
__device__ float g_inv[(size_t)kB * kC * kC];      // 1/sum_w exp (B,D,C)

__device__ __forceinline__ uint32_t smem_u32(const void* p) {
  uint32_t a;
  asm("{ .reg .u64 t; cvta.to.shared.u64 t, %1; cvt.u32.u64 %0, t; }" : "=r"(a) : "l"(p));
  return a;
}
__device__ __forceinline__ uint32_t f2tf32(float f) {
  uint32_t r;
  asm("cvt.rna.tf32.f32 %0, %1;" : "=r"(r) : "f"(f));
  return r;
}

// exp on the FMA pipe (no MUFU): exp(x) = 2^r * e^f, deg-5 Taylor on |f|<=ln2/2.
__device__ __forceinline__ float fast_exp(float x) {
  x = fminf(fmaxf(x, -30.f), 30.f);
  float r = rintf(x * 1.44269504f);
  float f = fmaf(r, -0.6931471805599453f, x);
  float p = 1.f + f * (1.f + f * (0.5f + f * (0.16666667f +
                f * (0.041666667f + f * 0.0083333333f))));
  return p * __int_as_float(((int)r + 127) << 23);
}

// SMEM row stride (words). 36 => ldmatrix phases span all 32 banks (4r+c).
constexpr int kLds = 36;
constexpr int kBufW = 128 * kLds;  // words per stage

// Load 16 k-words of one row into registers. KC=true: k unit stride (float4).
template <bool KC>
__device__ __forceinline__ void ldg16(float4 r[4], const float* __restrict__ p, long sK) {
  if (KC) {
#pragma unroll
    for (int i = 0; i < 4; i++) r[i] = reinterpret_cast<const float4*>(p)[i];
  } else {
#pragma unroll
    for (int i = 0; i < 4; i++) {
      r[i].x = p[(long)(i * 4 + 0) * sK];
      r[i].y = p[(long)(i * 4 + 1) * sK];
      r[i].z = p[(long)(i * 4 + 2) * sK];
      r[i].w = p[(long)(i * 4 + 3) * sK];
    }
  }
}

// Convert to tf32 (optionally *nrm first) and store 16 contiguous words to smem.
template <bool NORM>
__device__ __forceinline__ void sts16(uint32_t* __restrict__ dst, const float4 a[4],
                                      const float4 n[4]) {
#pragma unroll
  for (int i = 0; i < 4; i++) {
    float4 v = a[i];
    if (NORM) {
      v.x *= n[i].x; v.y *= n[i].y; v.z *= n[i].z; v.w *= n[i].w;
    }
    uint32_t t0 = f2tf32(v.x), t1 = f2tf32(v.y), t2 = f2tf32(v.z), t3 = f2tf32(v.w);
    asm volatile("st.shared.v4.b32 [%0], {%1,%2,%3,%4};"
                 :: "l"(dst + i * 4), "r"(t0), "r"(t1), "r"(t2), "r"(t3));
  }
}

__device__ __forceinline__ void ldsm_x4(uint32_t r[4], uint32_t addr) {
  asm volatile("ldmatrix.sync.aligned.m8n8.x4.shared.b16 {%0,%1,%2,%3}, [%4];"
               : "=r"(r[0]), "=r"(r[1]), "=r"(r[2]), "=r"(r[3]) : "r"(addr));
}
__device__ __forceinline__ void ldsm_x2(uint32_t r[2], uint32_t addr) {
  asm volatile("ldmatrix.sync.aligned.m8n8.x2.shared.b16 {%0,%1}, [%2];"
               : "=r"(r[0]), "=r"(r[1]) : "r"(addr));
}

// Core 128x128 GEMM body via mma.sync tf32 (fp32 accumulate).
// Register-staged double buffering + ldmatrix fragment loads.
//   C[m,n] = alpha * sum_k A[m*sAm+k*sAk] * B[n*sBn+k*sBk] (+biases) ; C[m + n*sCn]
// EEPI: epilogue writes fast_exp(alpha*acc). NORM: A *= nrm (same addressing).
template <bool AKC, bool BKC, bool NORM, bool EEPI>
__device__ __forceinline__ void gemm_body(
    const float* __restrict__ A, long sAm, long sAk,
    const float* __restrict__ Bp, long sBn, long sBk,
    float* __restrict__ Cp, long sCn,
    const float* __restrict__ nrm,
    const float* __restrict__ bias_m, const float* __restrict__ bias_n,
    float alpha, int K) {
  __shared__ uint32_t As[2][kBufW];
  __shared__ uint32_t Bs[2][kBufW];
  __shared__ float bmS[128], bnS[128];

  const int tid = threadIdx.x;
  const int lane = tid & 31, wid = tid >> 5;
  const int wm = (wid & 1) * 64, wn = (wid >> 1) * 32;
  const int row = tid >> 1, khalf = (tid & 1) * 16;

  if (!EEPI && tid < 128) {
    bmS[tid] = bias_m ? bias_m[tid] : 0.f;
    bnS[tid] = bias_n ? bias_n[tid] : 0.f;
  }

  const float* Arow = A + (long)row * sAm + (long)khalf * sAk;
  const float* Brow = Bp + (long)row * sBn + (long)khalf * sBk;
  const float* Nrow = NORM ? nrm + (long)row * sAm + (long)khalf * sAk : nullptr;
  uint32_t* const sA = &As[0][0] + row * kLds + khalf;
  uint32_t* const sB = &Bs[0][0] + row * kLds + khalf;

  // ldmatrix per-lane address offsets (bytes).
  const uint32_t a_off =
      (uint32_t)((((lane & 7) + ((lane >> 3) & 1) * 8) * kLds + (lane >> 4) * 4) * 4);
  const uint32_t b_off = (uint32_t)(((lane & 7) * kLds + ((lane >> 3) & 1) * 4) * 4);
  const uint32_t saA0 = smem_u32(As) + (uint32_t)(wm * kLds * 4) + a_off;
  const uint32_t saB0 = smem_u32(Bs) + (uint32_t)(wn * kLds * 4) + b_off;

  float4 pa[4], pb[4], pn[4];
  // Chunk 0.
  ldg16<AKC>(pa, Arow, sAk);
  ldg16<BKC>(pb, Brow, sBk);
  if (NORM) ldg16<AKC>(pn, Nrow, sAk);
  sts16<NORM>(sA, pa, pn);
  sts16<false>(sB, pb, nullptr);
  __syncthreads();

  float acc[4][4][4];
#pragma unroll
  for (int i = 0; i < 4; i++)
#pragma unroll
    for (int j = 0; j < 4; j++)
#pragma unroll
      for (int c = 0; c < 4; c++) acc[i][j][c] = 0.f;

  const int nch = K >> 5;
  for (int c = 0; c < nch; c++) {
    if (c + 1 < nch) {
      const long ko = (long)(c + 1) * 32;
      ldg16<AKC>(pa, Arow + ko * sAk, sAk);
      ldg16<BKC>(pb, Brow + ko * sBk, sBk);
      if (NORM) ldg16<AKC>(pn, Nrow + ko * sAk, sAk);
    }
    const uint32_t stg = (uint32_t)((c & 1) * kBufW * 4);
    const uint32_t aBase = saA0 + stg;
    const uint32_t bBase = saB0 + stg;

#pragma unroll
    for (int ks = 0; ks < 4; ks++) {
      uint32_t af[4][4], bf[4][2];
#pragma unroll
      for (int im = 0; im < 4; im++)
        ldsm_x4(af[im], aBase + (uint32_t)((im * 16 * kLds + ks * 8) * 4));
#pragma unroll
      for (int in = 0; in < 4; in++)
        ldsm_x2(bf[in], bBase + (uint32_t)((in * 8 * kLds + ks * 8) * 4));
#pragma unroll
      for (int im = 0; im < 4; im++)
#pragma unroll
        for (int in = 0; in < 4; in++) {
          asm volatile(
              "mma.sync.aligned.m16n8k8.row.col.f32.tf32.tf32.f32 "
              "{%0,%1,%2,%3}, {%4,%5,%6,%7}, {%8,%9}, {%0,%1,%2,%3};"
              : "+f"(acc[im][in][0]), "+f"(acc[im][in][1]), "+f"(acc[im][in][2]),
                "+f"(acc[im][in][3])
              : "r"(af[im][0]), "r"(af[im][1]), "r"(af[im][2]), "r"(af[im][3]),
                "r"(bf[in][0]), "r"(bf[in][1]));
        }
    }
    if (c + 1 < nch) {
      const int nb = (c + 1) & 1;
      sts16<NORM>(sA + nb * kBufW, pa, pn);
      sts16<false>(sB + nb * kBufW, pb, nullptr);
    }
    __syncthreads();
  }

  const int g = lane >> 2, t2 = (lane & 3) * 2;
#pragma unroll
  for (int im = 0; im < 4; im++) {
    int m0 = wm + im * 16 + g;
    int m1 = m0 + 8;
    float bm0 = EEPI ? 0.f : bmS[m0], bm1 = EEPI ? 0.f : bmS[m1];
#pragma unroll
    for (int in = 0; in < 4; in++) {
      int n0 = wn + in * 8 + t2;
      int n1 = n0 + 1;
      if (EEPI) {
        Cp[(long)n0 * sCn + m0] = fast_exp(alpha * acc[im][in][0]);
        Cp[(long)n1 * sCn + m0] = fast_exp(alpha * acc[im][in][1]);
        Cp[(long)n0 * sCn + m1] = fast_exp(alpha * acc[im][in][2]);
        Cp[(long)n1 * sCn + m1] = fast_exp(alpha * acc[im][in][3]);
      } else {
        float bn0 = bnS[n0], bn1 = bnS[n1];
        Cp[(long)n0 * sCn + m0] = alpha * acc[im][in][0] + bm0 + bn0;
        Cp[(long)n1 * sCn + m0] = alpha * acc[im][in][1] + bm0 + bn1;
        Cp[(long)n0 * sCn + m1] = alpha * acc[im][in][2] + bm1 + bn0;
        Cp[(long)n1 * sCn + m1] = alpha * acc[im][in][3] + bm1 + bn1;
      }
    }
  }
}

// Fused QKV: grid (1, 3, B*H); y selects weight/bias/output; x tile reused via L2.
__global__ __launch_bounds__(256) void gemm_qkv(
    const float* __restrict__ x,
    const float* __restrict__ Wq, const float* __restrict__ Wk, const float* __restrict__ Wv,
    const float* __restrict__ bq, const float* __restrict__ bk, const float* __restrict__ bv,
    float* __restrict__ q, float* __restrict__ k, float* __restrict__ v) {
  const int z = blockIdx.z, y = blockIdx.y;
  const float* A = (y == 0) ? Wq : (y == 1) ? Wk : Wv;
  const float* bm = (y == 0) ? bq : (y == 1) ? bk : bv;
  float* C = ((y == 0) ? q : (y == 1) ? k : v) +
             (long)(z / kH) * ((long)kW * kH * kC) + (long)(z % kH) * kC;
  const float* B = x + (long)z * kC * kW;
  gemm_body<false, false, false, false>(A, 1, kC, B, 1, kW, C, (long)kH * kC,
                                        nullptr, bm, nullptr, 1.f, kC);
}

template <bool AKC, bool BKC, bool NORM, bool EEPI>
__global__ __launch_bounds__(256) void gemm_gen(
    const float* __restrict__ A, int a_div, long a_so, long a_si, long sAm, long sAk,
    const float* __restrict__ Bp, int b_div, long b_so, long b_si, long sBn, long sBk,
    float* __restrict__ Cp, int c_div, long c_so, long c_si, long sCn,
    const float* __restrict__ nrm_base, int nrm_div,
    const float* __restrict__ bias_m, const float* __restrict__ bias_n,
    float alpha, int K) {
  const int z = blockIdx.z, bx = blockIdx.x, by = blockIdx.y;
  A += (long)(z / a_div) * a_so + (long)(z % a_div) * a_si + (long)bx * 128 * sAm;
  Bp += (long)(z / b_div) * b_so + (long)(z % b_div) * b_si + (long)by * 128 * sBn;
  Cp += (long)(z / c_div) * c_so + (long)(z % c_div) * c_si + (long)bx * 128 +
        (long)by * 128 * sCn;
  const float* nrm = nullptr;
  if (NORM) nrm = nrm_base + (long)(z / nrm_div) * kCC + (long)bx * 128 * sAm;
  gemm_body<AKC, BKC, NORM, EEPI>(A, sAm, sAk, Bp, sBn, sBk, Cp, sCn, nrm,
                                  bias_m ? bias_m + bx * 128 : nullptr,
                                  bias_n ? bias_n + by * 128 : nullptr, alpha, K);
}

// Per-(b,d,c) reciprocal of sum over w of exp(scores) stored in s (B,W,D,C).
__global__ __launch_bounds__(256) void softmax_sum(const float* __restrict__ s,
                                                   float* __restrict__ inv) {
  long t = (long)blockIdx.x * blockDim.x + threadIdx.x;  // < B*C*C
  int b = (int)(t / kCC);
  int r = (int)(t % kCC);
  const float* p = s + (long)b * kW * kCC + r;
  float l = 0.f;
#pragma unroll 8
  for (int w = 0; w < kW; w++) l += p[(long)w * kCC];
  inv[t] = 1.f / l;
}

// Transpose m5 (B,W,C,H) -> m6 (B,H,C,W).
__global__ __launch_bounds__(256) void trans_wh(const float* __restrict__ in,
                                                float* __restrict__ out) {
  __shared__ float tile[32][33];
  int bc = blockIdx.z;
  int b = bc / kC, c = bc % kC;
  long ibase = (long)b * kW * kC * kH + (long)c * kH;
  long obase = (long)b * kH * kC * kW + (long)c * kW;
  int w0 = blockIdx.x * 32, h0 = blockIdx.y * 32;
  int txl = threadIdx.x;
#pragma unroll
  for (int i = threadIdx.y; i < 32; i += 8)
    tile[i][txl] = in[ibase + (long)(w0 + i) * (kC * kH) + h0 + txl];
  __syncthreads();
#pragma unroll
  for (int i = threadIdx.y; i < 32; i += 8)
    out[obase + (long)(h0 + i) * (kC * kW) + w0 + txl] = tile[txl][i];
}

extern "C" void kernel_launch(void* const* d_in, const int* in_sizes, int n_in,
                              void* d_out, int out_size) {
  (void)in_sizes; (void)n_in; (void)out_size;
  const float* x  = (const float*)d_in[0];
  const float* Wq = (const float*)d_in[1];
  const float* bq = (const float*)d_in[2];
  const float* Wk = (const float*)d_in[3];
  const float* bk = (const float*)d_in[4];
  const float* Wv = (const float*)d_in[5];
  const float* bv = (const float*)d_in[6];
  const float* Wn = (const float*)d_in[7];
  const float* bn = (const float*)d_in[8];
  const float* Wo = (const float*)d_in[9];
  const float* bo = (const float*)d_in[10];
  float* out = (float*)d_out;

  float *q, *k, *v, *s, *wn, *inv;
  cudaGetSymbolAddress((void**)&q, g_q);
  cudaGetSymbolAddress((void**)&k, g_k);
  cudaGetSymbolAddress((void**)&v, g_v);
  cudaGetSymbolAddress((void**)&s, g_s);
  cudaGetSymbolAddress((void**)&wn, g_wn);
  cudaGetSymbolAddress((void**)&inv, g_inv);

  const long HC = (long)kH * kC;
  const long CW = (long)kC * kW;
  const long CC = kCC;
  const long CH = (long)kC * kH;

  // Pass 1: fused Q/K/V projections. z=(b*H+h), y selects head. m=d, n=w, k=c.
  gemm_qkv<<<dim3(1, 3, kB * kH), 256>>>(x, Wq, Wk, Wv, bq, bk, bv, q, k, v);

  // Pass 2: s[b,w][c,d] = exp(sum_h q*k / sqrt(W)). z=(b*W+w). m=c, n=d, k=h.
  gemm_gen<false, false, false, true><<<dim3(1, 1, kB * kW), 256>>>(
      q, 1, HC, 0, 1, kC,
      k, 1, HC, 0, 1, kC,
      s, 1, CC, 0, kC,
      nullptr, 1, nullptr, nullptr, 0.08838834764831845f, kH);

  // Pass 3: softmax denominators.
  softmax_sum<<<(int)((kB * CC) / 256), 256>>>(s, inv);

  // Pass 4: wn[b,w][c,e] = sum_d (e*inv)[d,c]*Wn[d,e] + bn[e]. m=c, n=e, k=d.
  gemm_gen<false, false, true, false><<<dim3(1, 1, kB * kW), 256>>>(
      s, 1, CC, 0, 1, kC,
      Wn, 1, 0, 0, 1, kC,
      wn, 1, CC, 0, kC,
      inv, kW, nullptr, bn, 1.f, kC);

  // Pass 5: m[b,w][h,c] = sum_e v[h,e]*wn[e,c]. m=h (grid.x=2), n=c, k=e.
  gemm_gen<true, false, false, false><<<dim3(2, 1, kB * kW), 256>>>(
      v, 1, HC, 0, kC, 1,
      wn, 1, CC, 0, 1, kC,
      q, 1, CH, 0, kH,
      nullptr, 1, nullptr, nullptr, 1.f, kC);

  // Pass 5.5: transpose m5 (B,W,C,H) -> m6 (B,H,C,W).
  trans_wh<<<dim3(kW / 32, kH / 32, kB * kC), dim3(32, 8)>>>(q, k);

  // Pass 6: out[b,h][w,o] = sum_c m6[c,w]*Wo[c,o] + bo[o]. m=w, n=o, k=c.
  gemm_gen<false, false, false, false><<<dim3(1, 1, kB * kH), 256>>>(
      k, 1, CW, 0, 1, kW,
      Wo, 1, 0, 0, 1, kC,
      out, 1, CW, 0, kW,
      nullptr, 1, nullptr, bo, 1.f, kC);
}